// round 1
// baseline (speedup 1.0000x reference)
#include <cuda_runtime.h>
#include <math.h>

#ifndef M_PI
#define M_PI 3.14159265358979323846
#endif

#define BB   8
#define TT   4096
#define EE   1024
#define HH   16
#define DD   64
#define KTOP 24

// ---------------- scratch (device globals: allowed, no runtime alloc) ----------------
__device__ float  g_Qt [BB * EE * TT];   // Q transposed: [b][e][t]
__device__ float  g_Kt [BB * EE * TT];   // K transposed: [b][e][t]
__device__ float  g_V  [BB * TT * EE];   // V normal:     [b][t][e]
__device__ float  g_agg[BB * TT * EE];   // aggregated:   [b][t][e]
__device__ float2 g_spec[BB * TT];       // per-batch accumulated spectrum
__device__ float2 g_tw [TT / 2];         // twiddles W_4096^j = exp(-2*pi*i*j/4096)
__device__ float  g_mean[BB * TT];       // mean autocorrelation per batch
__device__ float  g_topv[BB * KTOP];
__device__ int    g_topi[BB * KTOP];

// ---------------- init: zero spectrum accumulator + build twiddle table -------------
__global__ void init_kernel() {
    int i = blockIdx.x * blockDim.x + threadIdx.x;
    if (i < BB * TT) g_spec[i] = make_float2(0.f, 0.f);
    if (i < TT / 2) {
        double ang = -2.0 * M_PI * (double)i / (double)TT;
        double s, c;
        sincos(ang, &s, &c);
        g_tw[i] = make_float2((float)c, (float)s);
    }
}

// ---------------- fp32 SGEMM: C = A[M,K] * W[K,N] + bias -----------------------------
// M = 32768, K = 1024, N = 1024.  outmode 0: C[m*N+n].  outmode 1: C[((b*E+n)*T)+t].
__global__ void __launch_bounds__(256) sgemm_kernel(
    const float* __restrict__ A, const float* __restrict__ W,
    const float* __restrict__ bias, float* __restrict__ C, int outmode)
{
    __shared__ float As[8][128];
    __shared__ float Bs[8][128];

    const int tid  = threadIdx.x;
    const int m0   = blockIdx.y * 128;
    const int n0   = blockIdx.x * 128;
    const int ty   = tid >> 4;          // 0..15  (row group of 8)
    const int tx   = tid & 15;          // 0..15  (col group of 8)
    const int arow = tid >> 1;          // 0..127
    const int acol = (tid & 1) << 2;    // 0 or 4
    const int brow = tid >> 5;          // 0..7
    const int bcol = (tid & 31) << 2;   // 0..124

    const float* Aptr = A + (size_t)(m0 + arow) * 1024 + acol;
    const float* Wptr = W + (size_t)brow * 1024 + n0 + bcol;

    float4 a = *(const float4*)Aptr;
    float4 b = *(const float4*)Wptr;

    float acc[8][8];
#pragma unroll
    for (int i = 0; i < 8; i++)
#pragma unroll
        for (int j = 0; j < 8; j++) acc[i][j] = 0.f;

    for (int k0 = 0; k0 < 1024; k0 += 8) {
        As[acol + 0][arow] = a.x;
        As[acol + 1][arow] = a.y;
        As[acol + 2][arow] = a.z;
        As[acol + 3][arow] = a.w;
        *(float4*)&Bs[brow][bcol] = b;
        __syncthreads();

        if (k0 + 8 < 1024) {   // register prefetch of next tile
            a = *(const float4*)(Aptr + k0 + 8);
            b = *(const float4*)(Wptr + (size_t)(k0 + 8) * 1024);
        }

#pragma unroll
        for (int kk = 0; kk < 8; kk++) {
            float ra[8], rb[8];
#pragma unroll
            for (int i = 0; i < 8; i++) ra[i] = As[kk][ty * 8 + i];
#pragma unroll
            for (int j = 0; j < 8; j++) rb[j] = Bs[kk][tx * 8 + j];
#pragma unroll
            for (int i = 0; i < 8; i++)
#pragma unroll
                for (int j = 0; j < 8; j++)
                    acc[i][j] += ra[i] * rb[j];
        }
        __syncthreads();
    }

    if (outmode == 0) {
        // bias along n
        float bn[8];
#pragma unroll
        for (int j = 0; j < 8; j++) bn[j] = bias[n0 + tx * 8 + j];
#pragma unroll
        for (int i = 0; i < 8; i++) {
            size_t base = (size_t)(m0 + ty * 8 + i) * 1024 + n0 + tx * 8;
            float4 v0 = make_float4(acc[i][0] + bn[0], acc[i][1] + bn[1],
                                    acc[i][2] + bn[2], acc[i][3] + bn[3]);
            float4 v1 = make_float4(acc[i][4] + bn[4], acc[i][5] + bn[5],
                                    acc[i][6] + bn[6], acc[i][7] + bn[7]);
            *(float4*)&C[base]     = v0;
            *(float4*)&C[base + 4] = v1;
        }
    } else {
        // transposed per batch: C[((b*E + n) * T) + t], t contiguous per thread
        int bidx = m0 >> 12;             // 128 | 4096 so whole tile is one batch
        int t0   = (m0 & 4095) + ty * 8; // 8 consecutive t values per thread
#pragma unroll
        for (int j = 0; j < 8; j++) {
            int   n  = n0 + tx * 8 + j;
            float bn = bias[n];
            size_t base = ((size_t)(bidx * 1024 + n)) * 4096 + t0;
            float4 v0 = make_float4(acc[0][j] + bn, acc[1][j] + bn,
                                    acc[2][j] + bn, acc[3][j] + bn);
            float4 v1 = make_float4(acc[4][j] + bn, acc[5][j] + bn,
                                    acc[6][j] + bn, acc[7][j] + bn);
            *(float4*)&C[base]     = v0;
            *(float4*)&C[base + 4] = v1;
        }
    }
}

// ---------------- shared-memory 4096-pt radix-2 FFT (input pre-bit-reversed) --------
__device__ __forceinline__ void fft4096(float2* s, int tid, int nthreads) {
    int lm = 0;
    for (int m = 1; m < 4096; m <<= 1, lm++) {
        for (int i = tid; i < 2048; i += nthreads) {
            int j  = i & (m - 1);
            int i1 = ((i >> lm) << (lm + 1)) | j;
            int i2 = i1 + m;
            float2 w = g_tw[j << (11 - lm)];
            float2 u = s[i1];
            float2 v = s[i2];
            float vr = v.x * w.x - v.y * w.y;
            float vi = v.x * w.y + v.y * w.x;
            s[i1] = make_float2(u.x + vr, u.y + vi);
            s[i2] = make_float2(u.x - vr, u.y - vi);
        }
        __syncthreads();
    }
}

// ---------------- forward correlation spectrum: z = q + i*k pack trick ---------------
// 8 channels per block -> local accumulation in registers, 1/8 the atomics.
__global__ void __launch_bounds__(512) corrfft_kernel() {
    __shared__ float2 s[4096];
    const int tid = threadIdx.x;
    const int b   = blockIdx.x >> 7;          // 128 blocks per batch
    const int e0  = (blockIdx.x & 127) * 8;

    float2 psum[8];
#pragma unroll
    for (int r = 0; r < 8; r++) psum[r] = make_float2(0.f, 0.f);

    for (int c = 0; c < 8; c++) {
        const int ch = e0 + c;
        const float* q = g_Qt + ((size_t)(b * 1024 + ch)) * 4096;
        const float* k = g_Kt + ((size_t)(b * 1024 + ch)) * 4096;
        __syncthreads();   // previous product phase done before overwriting s
        for (int i = tid; i < 4096; i += 512) {
            int r = __brev(i) >> 20;
            s[r] = make_float2(q[i], k[i]);
        }
        __syncthreads();
        fft4096(s, tid, 512);
        // split packed spectrum, P = Qf * conj(Kf), accumulate
#pragma unroll
        for (int r = 0; r < 8; r++) {
            int f = tid + (r << 9);
            float2 A  = s[f];
            float2 Bc = s[(4096 - f) & 4095];
            float qr = 0.5f * (A.x + Bc.x);
            float qi = 0.5f * (A.y - Bc.y);
            float kr = 0.5f * (A.y + Bc.y);
            float ki = 0.5f * (Bc.x - A.x);
            psum[r].x += qr * kr + qi * ki;
            psum[r].y += qi * kr - qr * ki;
        }
    }

    float2* spec = g_spec + b * 4096;
#pragma unroll
    for (int r = 0; r < 8; r++) {
        int f = tid + (r << 9);
        atomicAdd(&spec[f].x, psum[r].x);
        atomicAdd(&spec[f].y, psum[r].y);
    }
}

// ---------------- inverse FFT of accumulated spectrum -> mean autocorrelation -------
__global__ void __launch_bounds__(512) ifft_kernel() {
    __shared__ float2 s[4096];
    const int b   = blockIdx.x;
    const int tid = threadIdx.x;
    for (int i = tid; i < 4096; i += 512) {
        int r = __brev(i) >> 20;
        float2 v = g_spec[b * 4096 + i];
        s[r] = make_float2(v.x, -v.y);     // conj -> forward fft -> Re == Re(ifft)*N
    }
    __syncthreads();
    fft4096(s, tid, 512);
    const float scale = 1.0f / ((float)TT * (float)EE);  // irfft 1/T  *  mean 1/(H*D)
    for (int i = tid; i < 4096; i += 512)
        g_mean[b * 4096 + i] = s[i].x * scale;
}

// ---------------- top-24 per batch (value desc, lowest index on ties) ----------------
__global__ void __launch_bounds__(256) topk_kernel() {
    __shared__ float sv[4096];
    __shared__ float rv[256];
    __shared__ int   ri[256];
    const int b   = blockIdx.x;
    const int tid = threadIdx.x;
    for (int i = tid; i < 4096; i += 256) sv[i] = g_mean[b * 4096 + i];
    __syncthreads();
    for (int kk = 0; kk < KTOP; kk++) {
        float best = -3.4e38f;
        int   bi   = 0;
        for (int i = tid; i < 4096; i += 256) {
            float v = sv[i];
            if (v > best) { best = v; bi = i; }   // ascending scan: first occurrence wins
        }
        rv[tid] = best; ri[tid] = bi;
        __syncthreads();
        for (int st = 128; st > 0; st >>= 1) {
            if (tid < st) {
                float ov = rv[tid + st]; int oi = ri[tid + st];
                if (ov > rv[tid] || (ov == rv[tid] && oi < ri[tid])) {
                    rv[tid] = ov; ri[tid] = oi;
                }
            }
            __syncthreads();
        }
        if (tid == 0) {
            g_topv[b * KTOP + kk] = rv[0];
            g_topi[b * KTOP + kk] = ri[0];
            sv[ri[0]] = -3.4e38f;
        }
        __syncthreads();
    }
}

// ---------------- aggregation: weighted circular-shift sum of V ----------------------
// agg[b,t,e] = sum_k w[g,k] * V[b,(t+d[g,k])%T,e],  g = (e/64) % 8   (torch repeat bug)
__global__ void __launch_bounds__(256) agg_kernel() {
    __shared__ float ws[8 * KTOP];
    __shared__ int   ds[8 * KTOP];
    const int tid = threadIdx.x;
    if (tid < 8 * KTOP) { ws[tid] = g_topv[tid]; ds[tid] = g_topi[tid]; }
    __syncthreads();

    const int bt = blockIdx.x;
    const int b  = bt >> 12;
    const int t  = bt & 4095;
    const int e4 = tid << 2;
    const int g  = (e4 >> 6) & 7;

    const float* Vb = g_V + (size_t)b * TT * EE;
    float4 acc = make_float4(0.f, 0.f, 0.f, 0.f);
#pragma unroll
    for (int kk = 0; kk < KTOP; kk++) {
        int   tk = (t + ds[g * KTOP + kk]) & 4095;
        float w  = ws[g * KTOP + kk];
        float4 v = *(const float4*)&Vb[(size_t)tk * EE + e4];
        acc.x += w * v.x; acc.y += w * v.y; acc.z += w * v.z; acc.w += w * v.w;
    }
    *(float4*)&g_agg[(size_t)bt * EE + e4] = acc;
}

// ---------------- launch --------------------------------------------------------------
extern "C" void kernel_launch(void* const* d_in, const int* in_sizes, int n_in,
                              void* d_out, int out_size) {
    (void)in_sizes; (void)n_in; (void)out_size;
    const float* hs = (const float*)d_in[0];
    const float* Wq = (const float*)d_in[1];
    const float* bq = (const float*)d_in[2];
    const float* Wk = (const float*)d_in[3];
    const float* bk = (const float*)d_in[4];
    const float* Wv = (const float*)d_in[5];
    const float* bv = (const float*)d_in[6];
    const float* Wo = (const float*)d_in[7];
    const float* bo = (const float*)d_in[8];
    float* out = (float*)d_out;

    void *pQt, *pKt, *pV, *pAgg;
    cudaGetSymbolAddress(&pQt,  g_Qt);
    cudaGetSymbolAddress(&pKt,  g_Kt);
    cudaGetSymbolAddress(&pV,   g_V);
    cudaGetSymbolAddress(&pAgg, g_agg);

    init_kernel<<<(BB * TT + 255) / 256, 256>>>();

    dim3 ggrid(EE / 128, (BB * TT) / 128);
    sgemm_kernel<<<ggrid, 256>>>(hs, Wq, bq, (float*)pQt, 1);
    sgemm_kernel<<<ggrid, 256>>>(hs, Wk, bk, (float*)pKt, 1);
    sgemm_kernel<<<ggrid, 256>>>(hs, Wv, bv, (float*)pV,  0);

    corrfft_kernel<<<BB * 128, 512>>>();
    ifft_kernel<<<BB, 512>>>();
    topk_kernel<<<BB, 256>>>();
    agg_kernel<<<BB * TT, 256>>>();

    sgemm_kernel<<<ggrid, 256>>>((const float*)pAgg, Wo, bo, out, 0);
}

// round 3
// speedup vs baseline: 2.6104x; 2.6104x over previous
#include <cuda_runtime.h>
#include <math.h>
#include <stdint.h>

#ifndef M_PI
#define M_PI 3.14159265358979323846
#endif

#define BB   8
#define TT   4096
#define EE   1024
#define HH   16
#define DD   64
#define KTOP 24

// ===================== scratch (device globals) =====================
__device__ float  g_X  [BB * TT * EE];   // tf32-rounded hidden_states
__device__ float  g_Wt [EE * EE];        // current transposed+rounded weight
__device__ float  g_Qt [BB * EE * TT];   // Q transposed: [b][e][t]
__device__ float  g_Kt [BB * EE * TT];   // K transposed: [b][e][t]
__device__ float  g_V  [BB * TT * EE];   // V normal:     [b][t][e]
__device__ float  g_agg[BB * TT * EE];   // aggregated (tf32-rounded)
__device__ float2 g_spec[BB * TT];
__device__ float2 g_tw [TT / 2];
__device__ float  g_mean[BB * TT];
__device__ float  g_topv[BB * KTOP];
__device__ int    g_topi[BB * KTOP];

// ===================== helpers =====================
__device__ __forceinline__ float tf32r(float x) {
    uint32_t u;
    asm("cvt.rna.tf32.f32 %0, %1;" : "=r"(u) : "f"(x));
    return __uint_as_float(u);
}
#define CP16(saddr, gptr) \
    asm volatile("cp.async.cg.shared.global [%0], [%1], 16;" :: "r"(saddr), "l"(gptr) : "memory")
#define CP_COMMIT() asm volatile("cp.async.commit_group;" ::: "memory")
#define CP_WAIT1()  asm volatile("cp.async.wait_group 1;" ::: "memory")

__device__ __forceinline__ uint32_t smem_u32(const void* p) {
    uint32_t a;
    asm("{ .reg .u64 t; cvta.to.shared.u64 t, %1; cvt.u32.u64 %0, t; }" : "=r"(a) : "l"(p));
    return a;
}

__device__ __forceinline__ void mma_tf32(float* d, const uint32_t* a, const uint32_t* b) {
    asm volatile(
        "mma.sync.aligned.m16n8k8.row.col.f32.tf32.tf32.f32 "
        "{%0,%1,%2,%3}, {%4,%5,%6,%7}, {%8,%9}, {%0,%1,%2,%3};"
        : "+f"(d[0]), "+f"(d[1]), "+f"(d[2]), "+f"(d[3])
        : "r"(a[0]), "r"(a[1]), "r"(a[2]), "r"(a[3]), "r"(b[0]), "r"(b[1]));
}

// ===================== init =====================
__global__ void init_kernel() {
    int i = blockIdx.x * blockDim.x + threadIdx.x;
    if (i < BB * TT) g_spec[i] = make_float2(0.f, 0.f);
    if (i < TT / 2) {
        double ang = -2.0 * M_PI * (double)i / (double)TT;
        double s, c;
        sincos(ang, &s, &c);
        g_tw[i] = make_float2((float)c, (float)s);
    }
}

__global__ void __launch_bounds__(256) round_x_kernel(const float* __restrict__ src) {
    int i = blockIdx.x * blockDim.x + threadIdx.x;
    float4 v = ((const float4*)src)[i];
    v.x = tf32r(v.x); v.y = tf32r(v.y); v.z = tf32r(v.z); v.w = tf32r(v.w);
    ((float4*)g_X)[i] = v;
}

// Wt[n][k] = round_tf32(W[k][n])
__global__ void __launch_bounds__(256) transpose_round_kernel(const float* __restrict__ W) {
    __shared__ float ts[32][33];
    int x  = blockIdx.x * 32 + threadIdx.x;   // n
    int y0 = blockIdx.y * 32;                 // k
    for (int i = threadIdx.y; i < 32; i += 8)
        ts[i][threadIdx.x] = W[(size_t)(y0 + i) * EE + x];
    __syncthreads();
    int xo = y0 + threadIdx.x;                // k out
    int yo = blockIdx.x * 32;                 // n out
    for (int i = threadIdx.y; i < 32; i += 8)
        g_Wt[(size_t)(yo + i) * EE + xo] = tf32r(ts[threadIdx.x][i]);
}

// ===================== tf32 mma.sync GEMM =====================
// C[M=32768, N=1024] = A[M,K=1024] * Bt[N,K]^T + bias
// CTA 128x256, warp 64x64 (2x4 warps), K staged 32, 3-stage cp.async.
#define BM 128
#define BN 256
#define BK 32
#define NSTG 3
#define A_STRIDE 36            // floats per A row in smem (conflict-free)
#define B_STRIDE 36
#define A_FLOATS (BM * A_STRIDE)   // 4608
#define B_FLOATS (BN * B_STRIDE)   // 9216
#define STG_FLOATS (A_FLOATS + B_FLOATS)   // 13824
#define GEMM_SMEM (NSTG * STG_FLOATS * 4)  // 165888 B

__global__ void __launch_bounds__(256, 1)
tf32_gemm_kernel(const float* __restrict__ A, const float* __restrict__ Bt,
                 const float* __restrict__ bias, float* __restrict__ C, int outmode)
{
    extern __shared__ float smem[];
    const int tid  = threadIdx.x;
    const int wid  = tid >> 5;
    const int lane = tid & 31;
    const int g    = lane >> 2;     // 0..7
    const int t4   = lane & 3;      // 0..3
    const int m0   = blockIdx.y * BM;
    const int n0   = blockIdx.x * BN;
    const int wm   = (wid >> 2) * 64;
    const int wn   = (wid & 3) * 64;

    const float* gA = A  + (size_t)m0 * EE;
    const float* gB = Bt + (size_t)n0 * EE;

    const uint32_t sbase = smem_u32(smem);
    const int arow = tid >> 3;          // 0..31  (row step 32)
    const int ac4  = (tid & 7) << 2;    // float offset 0..28

    // load K-block kt into stage buffer
    auto load_stage = [&](int kt) {
        const int st = kt % NSTG;
        const uint32_t sA = sbase + st * STG_FLOATS * 4;
        const uint32_t sB = sA + A_FLOATS * 4;
        const float* ga = gA + kt * BK;
        const float* gb = gB + kt * BK;
#pragma unroll
        for (int i = 0; i < 4; i++) {           // A: 128 rows
            int r = arow + i * 32;
            CP16(sA + (r * A_STRIDE + ac4) * 4, ga + (size_t)r * EE + ac4);
        }
#pragma unroll
        for (int i = 0; i < 8; i++) {           // B: 256 rows
            int r = arow + i * 32;
            CP16(sB + (r * B_STRIDE + ac4) * 4, gb + (size_t)r * EE + ac4);
        }
    };

    float acc[4][8][4];
#pragma unroll
    for (int mt = 0; mt < 4; mt++)
#pragma unroll
        for (int nt = 0; nt < 8; nt++)
#pragma unroll
            for (int i = 0; i < 4; i++) acc[mt][nt][i] = 0.f;

    load_stage(0); CP_COMMIT();
    load_stage(1); CP_COMMIT();

    const int KT = EE / BK;   // 32
    for (int kt = 0; kt < KT; kt++) {
        CP_WAIT1();
        __syncthreads();
        if (kt + 2 < KT) load_stage(kt + 2);
        CP_COMMIT();

        const float* As = smem + (kt % NSTG) * STG_FLOATS;
        const float* Bs = As + A_FLOATS;

#pragma unroll
        for (int ks = 0; ks < 4; ks++) {
            const int kk = ks * 8;
            uint32_t af[4][4], bf[8][2];
#pragma unroll
            for (int mt = 0; mt < 4; mt++) {
                const float* ap = As + (wm + mt * 16 + g) * A_STRIDE + kk + t4;
                af[mt][0] = __float_as_uint(ap[0]);
                af[mt][1] = __float_as_uint(ap[8 * A_STRIDE]);
                af[mt][2] = __float_as_uint(ap[4]);
                af[mt][3] = __float_as_uint(ap[8 * A_STRIDE + 4]);
            }
#pragma unroll
            for (int nt = 0; nt < 8; nt++) {
                const float* bp = Bs + (wn + nt * 8 + g) * B_STRIDE + kk + t4;
                bf[nt][0] = __float_as_uint(bp[0]);
                bf[nt][1] = __float_as_uint(bp[4]);
            }
#pragma unroll
            for (int mt = 0; mt < 4; mt++)
#pragma unroll
                for (int nt = 0; nt < 8; nt++)
                    mma_tf32(acc[mt][nt], af[mt], bf[nt]);
        }
        __syncthreads();
    }

    // ---- epilogue ----
    if (outmode == 0) {
#pragma unroll
        for (int nt = 0; nt < 8; nt++) {
            const int n  = n0 + wn + nt * 8 + 2 * t4;
            const float b0 = __ldg(bias + n);
            const float b1 = __ldg(bias + n + 1);
#pragma unroll
            for (int mt = 0; mt < 4; mt++) {
                const int mrow = m0 + wm + mt * 16 + g;
                float2 v0 = make_float2(acc[mt][nt][0] + b0, acc[mt][nt][1] + b1);
                float2 v1 = make_float2(acc[mt][nt][2] + b0, acc[mt][nt][3] + b1);
                *(float2*)&C[(size_t)mrow * EE + n]       = v0;
                *(float2*)&C[(size_t)(mrow + 8) * EE + n] = v1;
            }
        }
    } else {
        // transposed per batch: C[((b*E + n) * T) + t]
        const int bbv   = m0 >> 12;
        const int tbase = (m0 & 4095) + wm;
#pragma unroll
        for (int nt = 0; nt < 8; nt++) {
            const int n  = n0 + wn + nt * 8 + 2 * t4;
            const float b0 = __ldg(bias + n);
            const float b1 = __ldg(bias + n + 1);
            float* c0 = C + ((size_t)(bbv * EE + n) << 12);
            float* c1 = C + ((size_t)(bbv * EE + n + 1) << 12);
#pragma unroll
            for (int mt = 0; mt < 4; mt++) {
                const int t = tbase + mt * 16 + g;
                c0[t]     = acc[mt][nt][0] + b0;
                c1[t]     = acc[mt][nt][1] + b1;
                c0[t + 8] = acc[mt][nt][2] + b0;
                c1[t + 8] = acc[mt][nt][3] + b1;
            }
        }
    }
}

// ===================== FFT autocorrelation path (fp32) =====================
__device__ __forceinline__ void fft4096(float2* s, int tid, int nthreads) {
    int lm = 0;
    for (int m = 1; m < 4096; m <<= 1, lm++) {
        for (int i = tid; i < 2048; i += nthreads) {
            int j  = i & (m - 1);
            int i1 = ((i >> lm) << (lm + 1)) | j;
            int i2 = i1 + m;
            float2 w = g_tw[j << (11 - lm)];
            float2 u = s[i1];
            float2 v = s[i2];
            float vr = v.x * w.x - v.y * w.y;
            float vi = v.x * w.y + v.y * w.x;
            s[i1] = make_float2(u.x + vr, u.y + vi);
            s[i2] = make_float2(u.x - vr, u.y - vi);
        }
        __syncthreads();
    }
}

__global__ void __launch_bounds__(512) corrfft_kernel() {
    __shared__ float2 s[4096];
    const int tid = threadIdx.x;
    const int b   = blockIdx.x >> 7;
    const int e0  = (blockIdx.x & 127) * 8;

    float2 psum[8];
#pragma unroll
    for (int r = 0; r < 8; r++) psum[r] = make_float2(0.f, 0.f);

    for (int c = 0; c < 8; c++) {
        const int ch = e0 + c;
        const float* q = g_Qt + ((size_t)(b * 1024 + ch)) * 4096;
        const float* k = g_Kt + ((size_t)(b * 1024 + ch)) * 4096;
        __syncthreads();
        for (int i = tid; i < 4096; i += 512) {
            int r = __brev(i) >> 20;
            s[r] = make_float2(q[i], k[i]);
        }
        __syncthreads();
        fft4096(s, tid, 512);
#pragma unroll
        for (int r = 0; r < 8; r++) {
            int f = tid + (r << 9);
            float2 A  = s[f];
            float2 Bc = s[(4096 - f) & 4095];
            float qr = 0.5f * (A.x + Bc.x);
            float qi = 0.5f * (A.y - Bc.y);
            float kr = 0.5f * (A.y + Bc.y);
            float ki = 0.5f * (Bc.x - A.x);
            psum[r].x += qr * kr + qi * ki;
            psum[r].y += qi * kr - qr * ki;
        }
    }

    float2* spec = g_spec + b * 4096;
#pragma unroll
    for (int r = 0; r < 8; r++) {
        int f = tid + (r << 9);
        atomicAdd(&spec[f].x, psum[r].x);
        atomicAdd(&spec[f].y, psum[r].y);
    }
}

__global__ void __launch_bounds__(512) ifft_kernel() {
    __shared__ float2 s[4096];
    const int b   = blockIdx.x;
    const int tid = threadIdx.x;
    for (int i = tid; i < 4096; i += 512) {
        int r = __brev(i) >> 20;
        float2 v = g_spec[b * 4096 + i];
        s[r] = make_float2(v.x, -v.y);
    }
    __syncthreads();
    fft4096(s, tid, 512);
    const float scale = 1.0f / ((float)TT * (float)EE);
    for (int i = tid; i < 4096; i += 512)
        g_mean[b * 4096 + i] = s[i].x * scale;
}

__global__ void __launch_bounds__(256) topk_kernel() {
    __shared__ float sv[4096];
    __shared__ float rv[256];
    __shared__ int   ri[256];
    const int b   = blockIdx.x;
    const int tid = threadIdx.x;
    for (int i = tid; i < 4096; i += 256) sv[i] = g_mean[b * 4096 + i];
    __syncthreads();
    for (int kk = 0; kk < KTOP; kk++) {
        float best = -3.4e38f;
        int   bi   = 0;
        for (int i = tid; i < 4096; i += 256) {
            float v = sv[i];
            if (v > best) { best = v; bi = i; }
        }
        rv[tid] = best; ri[tid] = bi;
        __syncthreads();
        for (int st = 128; st > 0; st >>= 1) {
            if (tid < st) {
                float ov = rv[tid + st]; int oi = ri[tid + st];
                if (ov > rv[tid] || (ov == rv[tid] && oi < ri[tid])) {
                    rv[tid] = ov; ri[tid] = oi;
                }
            }
            __syncthreads();
        }
        if (tid == 0) {
            g_topv[b * KTOP + kk] = rv[0];
            g_topi[b * KTOP + kk] = ri[0];
            sv[ri[0]] = -3.4e38f;
        }
        __syncthreads();
    }
}

// agg[b,t,e] = sum_k w[g,k] * V[b,(t+d[g,k])%T,e],  g = (e/64) % 8; tf32-rounded
__global__ void __launch_bounds__(256) agg_kernel() {
    __shared__ float ws[8 * KTOP];
    __shared__ int   ds[8 * KTOP];
    const int tid = threadIdx.x;
    if (tid < 8 * KTOP) { ws[tid] = g_topv[tid]; ds[tid] = g_topi[tid]; }
    __syncthreads();

    const int bt = blockIdx.x;
    const int b  = bt >> 12;
    const int t  = bt & 4095;
    const int e4 = tid << 2;
    const int gg = (e4 >> 6) & 7;

    const float* Vb = g_V + (size_t)b * TT * EE;
    float4 acc = make_float4(0.f, 0.f, 0.f, 0.f);
#pragma unroll
    for (int kk = 0; kk < KTOP; kk++) {
        int   tk = (t + ds[gg * KTOP + kk]) & 4095;
        float w  = ws[gg * KTOP + kk];
        float4 v = *(const float4*)&Vb[(size_t)tk * EE + e4];
        acc.x += w * v.x; acc.y += w * v.y; acc.z += w * v.z; acc.w += w * v.w;
    }
    acc.x = tf32r(acc.x); acc.y = tf32r(acc.y);
    acc.z = tf32r(acc.z); acc.w = tf32r(acc.w);
    *(float4*)&g_agg[(size_t)bt * EE + e4] = acc;
}

// ===================== launch =====================
extern "C" void kernel_launch(void* const* d_in, const int* in_sizes, int n_in,
                              void* d_out, int out_size) {
    (void)in_sizes; (void)n_in; (void)out_size;
    const float* hs = (const float*)d_in[0];
    const float* Wq = (const float*)d_in[1];
    const float* bq = (const float*)d_in[2];
    const float* Wk = (const float*)d_in[3];
    const float* bk = (const float*)d_in[4];
    const float* Wv = (const float*)d_in[5];
    const float* bv = (const float*)d_in[6];
    const float* Wo = (const float*)d_in[7];
    const float* bo = (const float*)d_in[8];
    float* out = (float*)d_out;

    cudaFuncSetAttribute(tf32_gemm_kernel,
                         cudaFuncAttributeMaxDynamicSharedMemorySize, GEMM_SMEM);

    void *pX, *pWt, *pQt, *pKt, *pV, *pAgg;
    cudaGetSymbolAddress(&pX,   g_X);
    cudaGetSymbolAddress(&pWt,  g_Wt);
    cudaGetSymbolAddress(&pQt,  g_Qt);
    cudaGetSymbolAddress(&pKt,  g_Kt);
    cudaGetSymbolAddress(&pV,   g_V);
    cudaGetSymbolAddress(&pAgg, g_agg);

    init_kernel<<<(BB * TT + 255) / 256, 256>>>();
    round_x_kernel<<<(BB * TT * EE / 4) / 256, 256>>>(hs);

    const dim3 tgrid(EE / 32, EE / 32);
    const dim3 tblk(32, 8);
    const dim3 ggrid(EE / BN, (BB * TT) / BM);

    transpose_round_kernel<<<tgrid, tblk>>>(Wq);
    tf32_gemm_kernel<<<ggrid, 256, GEMM_SMEM>>>((const float*)pX, (const float*)pWt, bq, (float*)pQt, 1);

    transpose_round_kernel<<<tgrid, tblk>>>(Wk);
    tf32_gemm_kernel<<<ggrid, 256, GEMM_SMEM>>>((const float*)pX, (const float*)pWt, bk, (float*)pKt, 1);

    transpose_round_kernel<<<tgrid, tblk>>>(Wv);
    tf32_gemm_kernel<<<ggrid, 256, GEMM_SMEM>>>((const float*)pX, (const float*)pWt, bv, (float*)pV, 0);

    corrfft_kernel<<<BB * 128, 512>>>();
    ifft_kernel<<<BB, 512>>>();
    topk_kernel<<<BB, 256>>>();
    agg_kernel<<<BB * TT, 256>>>();

    transpose_round_kernel<<<tgrid, tblk>>>(Wo);
    tf32_gemm_kernel<<<ggrid, 256, GEMM_SMEM>>>((const float*)pAgg, (const float*)pWt, bo, out, 0);
}